// round 10
// baseline (speedup 1.0000x reference)
#include <cuda_runtime.h>
#include <math.h>

#define TINF 3.0e38f
#define TT   1024
#define BB   32
#define DDIM 64
#define RS   1024        // floats per diag row (128B-aligned rows)
#define DROWS 2120       // 2047 used + pipeline pad (max row touched = 2115)

// Diag-major cost [b][d][j]. Valid cells written by cost_kernel; invalid cells
// pre-filled TINF by init_kernel (rows >= 2047 uninitialized: provably never
// influence the result; fmin/fmax are NaN-safe).
__device__ float g_cost[(size_t)BB * DROWS * RS];
__device__ float g_n2[2 * BB * TT];
__device__ float g_bdist[BB];

// ---------------------------------------------------------------------------
// Kernel 0: TINF only where needed (d in [0, 2047)).
// ---------------------------------------------------------------------------
__global__ void init_kernel() {
    int d = blockIdx.x, b = blockIdx.y;
    float* row = g_cost + ((size_t)b * DROWS + d) * RS;
    int s, e;
    if (d < 1023)        { s = d + 1; e = 1024; }
    else if (d == 1023)  { return; }
    else                 { s = 0; e = d - 1023; }
    for (int j = s + threadIdx.x; j < e; j += 256) row[j] = TINF;
}

// ---------------------------------------------------------------------------
// Kernel 1: squared row norms. One warp per 64-dim row.
// ---------------------------------------------------------------------------
__global__ void norms_kernel(const float* __restrict__ pred,
                             const float* __restrict__ targ) {
    int gw   = (blockIdx.x * blockDim.x + threadIdx.x) >> 5;
    int lane = threadIdx.x & 31;
    if (gw >= 2 * BB * TT) return;
    const float* src = (gw < BB * TT) ? (pred + (size_t)gw * DDIM)
                                      : (targ + (size_t)(gw - BB * TT) * DDIM);
    float x0 = src[lane], x1 = src[lane + 32];
    float s = x0 * x0 + x1 * x1;
    #pragma unroll
    for (int o = 16; o > 0; o >>= 1) s += __shfl_down_sync(0xffffffffu, s, o);
    if (lane == 0) g_n2[gw] = s;
}

// ---------------------------------------------------------------------------
// Kernel 2: TF32 tensor-core cost tiles (unchanged from R7).
// ---------------------------------------------------------------------------
__device__ __forceinline__ unsigned f2tf(float x) {
    unsigned u;
    asm("cvt.rna.tf32.f32 %0, %1;" : "=r"(u) : "f"(x));
    return u;
}
__device__ __forceinline__ void mma_tf32(float c[4], const unsigned a[4],
                                         const unsigned b[2]) {
    asm volatile(
        "mma.sync.aligned.m16n8k8.row.col.f32.tf32.tf32.f32 "
        "{%0,%1,%2,%3}, {%4,%5,%6,%7}, {%8,%9}, {%0,%1,%2,%3};"
        : "+f"(c[0]), "+f"(c[1]), "+f"(c[2]), "+f"(c[3])
        : "r"(a[0]), "r"(a[1]), "r"(a[2]), "r"(a[3]), "r"(b[0]), "r"(b[1]));
}

#define SKP 36   // smem k-stride (32 + 4 pad)

__global__ void __launch_bounds__(256, 2) cost_kernel(const float* __restrict__ pred,
                                                      const float* __restrict__ targ) {
    int b  = blockIdx.z;
    int i0 = blockIdx.y * 128, j0 = blockIdx.x * 128;
    const float* A  = pred + (size_t)b * TT * DDIM;
    const float* Bm = targ + (size_t)b * TT * DDIM;

    __shared__ __align__(16) float smbuf[2 * 128 * SKP];   // 36864 B
    float* sA = smbuf;
    float* sB = smbuf + 128 * SKP;
    float* Cs = smbuf;                                     // reused in epilogue

    int tid  = threadIdx.x;
    int lane = tid & 31, w = tid >> 5;
    int g    = lane >> 2, tig = lane & 3;
    int wm   = (w & 3) * 32, wn = (w >> 2) * 64;

    float c[2][8][4];
    #pragma unroll
    for (int mt = 0; mt < 2; ++mt)
        #pragma unroll
        for (int nt = 0; nt < 8; ++nt)
            #pragma unroll
            for (int e = 0; e < 4; ++e) c[mt][nt][e] = 0.f;

    int lr = tid >> 1;
    int lk = (tid & 1) * 16;
    const float* ga = A  + (size_t)(i0 + lr) * DDIM + lk;
    const float* gb = Bm + (size_t)(j0 + lr) * DDIM + lk;

    #pragma unroll 1
    for (int kc = 0; kc < 64; kc += 32) {
        #pragma unroll
        for (int c4 = 0; c4 < 4; ++c4) {
            float4 va = *(const float4*)(ga + kc + c4 * 4);
            float4 vb = *(const float4*)(gb + kc + c4 * 4);
            int o = lr * SKP + lk + c4 * 4;
            sA[o + 0] = __uint_as_float(f2tf(va.x));
            sA[o + 1] = __uint_as_float(f2tf(va.y));
            sA[o + 2] = __uint_as_float(f2tf(va.z));
            sA[o + 3] = __uint_as_float(f2tf(va.w));
            sB[o + 0] = __uint_as_float(f2tf(vb.x));
            sB[o + 1] = __uint_as_float(f2tf(vb.y));
            sB[o + 2] = __uint_as_float(f2tf(vb.z));
            sB[o + 3] = __uint_as_float(f2tf(vb.w));
        }
        __syncthreads();

        #pragma unroll
        for (int ks = 0; ks < 32; ks += 8) {
            unsigned af[2][4], bf[8][2];
            #pragma unroll
            for (int mt = 0; mt < 2; ++mt) {
                int mr = wm + mt * 16;
                af[mt][0] = __float_as_uint(sA[(mr + g)     * SKP + ks + tig]);
                af[mt][1] = __float_as_uint(sA[(mr + g + 8) * SKP + ks + tig]);
                af[mt][2] = __float_as_uint(sA[(mr + g)     * SKP + ks + tig + 4]);
                af[mt][3] = __float_as_uint(sA[(mr + g + 8) * SKP + ks + tig + 4]);
            }
            #pragma unroll
            for (int nt = 0; nt < 8; ++nt) {
                int nr = wn + nt * 8 + g;
                bf[nt][0] = __float_as_uint(sB[nr * SKP + ks + tig]);
                bf[nt][1] = __float_as_uint(sB[nr * SKP + ks + tig + 4]);
            }
            #pragma unroll
            for (int mt = 0; mt < 2; ++mt)
                #pragma unroll
                for (int nt = 0; nt < 8; ++nt)
                    mma_tf32(c[mt][nt], af[mt], bf[nt]);
        }
        __syncthreads();
    }

    float a2v[2][2], b2v[8][2];
    #pragma unroll
    for (int mt = 0; mt < 2; ++mt) {
        a2v[mt][0] = g_n2[b * TT + i0 + wm + mt * 16 + g];
        a2v[mt][1] = g_n2[b * TT + i0 + wm + mt * 16 + g + 8];
    }
    #pragma unroll
    for (int nt = 0; nt < 8; ++nt) {
        b2v[nt][0] = g_n2[BB * TT + b * TT + j0 + wn + nt * 8 + 2 * tig];
        b2v[nt][1] = g_n2[BB * TT + b * TT + j0 + wn + nt * 8 + 2 * tig + 1];
    }

    float* out = g_cost + (size_t)b * DROWS * RS;

    #pragma unroll 1
    for (int qq = 0; qq < 4; ++qq) {
        int qi = qq >> 1, qj = qq & 1;
        __syncthreads();
        if ((w >> 2) == qj && ((w & 3) >> 1) == qi) {
            int mloc0 = ((w & 3) & 1) * 32;
            #pragma unroll
            for (int mt = 0; mt < 2; ++mt) {
                int ml = mloc0 + mt * 16 + g;
                #pragma unroll
                for (int nt = 0; nt < 8; ++nt) {
                    int nl = nt * 8 + 2 * tig;
                    float s0 = a2v[mt][0] + b2v[nt][0] - 2.0f * c[mt][nt][0];
                    float s1 = a2v[mt][0] + b2v[nt][1] - 2.0f * c[mt][nt][1];
                    float s2 = a2v[mt][1] + b2v[nt][0] - 2.0f * c[mt][nt][2];
                    float s3 = a2v[mt][1] + b2v[nt][1] - 2.0f * c[mt][nt][3];
                    Cs[ml * 66 + nl]           = sqrtf(fmaxf(s0, 1e-12f));
                    Cs[ml * 66 + nl + 1]       = sqrtf(fmaxf(s1, 1e-12f));
                    Cs[(ml + 8) * 66 + nl]     = sqrtf(fmaxf(s2, 1e-12f));
                    Cs[(ml + 8) * 66 + nl + 1] = sqrtf(fmaxf(s3, 1e-12f));
                }
            }
        }
        __syncthreads();

        int i0q = i0 + qi * 64, j0q = j0 + qj * 64;
        int D0 = i0q + j0q;
        for (int dd = w; dd < 127; dd += 8) {
            int jl = max(0, dd - 63);
            int jh = min(dd, 63);
            int L = jh - jl + 1;
            size_t gbase = (size_t)(D0 + dd) * RS + (size_t)(j0q + jl);
            for (int l = lane; l < L; l += 32) {
                int j = jl + l;
                out[gbase + l] = Cs[(dd - j) * 66 + j];
            }
        }
    }
}

// ---------------------------------------------------------------------------
// Kernel 3: wavefront DP with a 10-stage cp.async smem pipeline (depth 9
// supersteps = 36 cost rows in flight per thread; zero register cost).
// Stage = 4 diag rows, each row stored as [4-float TINF guard | 1024 data]
// so the t=0 halo is branch-free and halo reads stay 16B-aligned.
// Superstep math identical to R7/R9 (halo now read from neighbor's staged
// data instead of shfl). One barrier per superstep, proven race-free:
// issue at body s targets the buffer last consumed at body s-1, and
// barrier_s orders all of body s-1 before any body-s issue.
// ---------------------------------------------------------------------------
#define RING    10
#define SROW    1028                 // floats per staged row (4 guard + 1024)
#define SSTAGE  (4 * SROW)           // floats per stage
#define DPDYN   (RING * SSTAGE * 4)  // dynamic smem bytes (164,480)

__device__ __forceinline__ void cpa16(unsigned dst, const float* src) {
    asm volatile("cp.async.cg.shared.global [%0], [%1], 16;"
                 :: "r"(dst), "l"(src));
}

__global__ void __launch_bounds__(256, 1) dp_kernel() {
    extern __shared__ float dsm[];
    int b  = blockIdx.x;
    int t  = threadIdx.x;
    int j0 = t << 2;
    const float* SCo = g_cost + (size_t)b * DROWS * RS + j0;

    __shared__ float4 sp[2][257], sq[2][257];
    for (int i = t; i < 2 * 257; i += 256) {
        (&sp[0][0])[i] = make_float4(TINF, TINF, TINF, TINF);
        (&sq[0][0])[i] = make_float4(TINF, TINF, TINF, TINF);
    }
    for (int i = t; i < RING * 4; i += 256) {     // per-row TINF guards
        float* gr = dsm + i * SROW;
        gr[0] = TINF; gr[1] = TINF; gr[2] = TINF; gr[3] = TINF;
    }
    __syncthreads();

    unsigned smu = (unsigned)__cvta_generic_to_shared(dsm) + (4 + j0) * 4;

    // Prologue: issue stages 0..8 (one commit group per stage).
    for (int s = 0; s < RING - 1; ++s) {
        const float* src = SCo + (size_t)(4 * s) * RS;
        unsigned d = smu + s * (SSTAGE * 4);
        #pragma unroll
        for (int k = 0; k < 4; ++k)
            cpa16(d + k * (SROW * 4), src + (size_t)k * RS);
        asm volatile("cp.async.commit_group;");
    }

    float p[4] = {TINF, TINF, TINF, TINF};
    float q[4] = {TINF, TINF, TINF, TINF};
    float res  = 0.f;
    int stage  = 0;

    // 520 supersteps x 4 diagonals = 2080 >= 2047. Max row issued: 2115.
    #pragma unroll 1
    for (int s = 0; s < 520; ++s) {
        asm volatile("cp.async.wait_group 8;");
        __syncthreads();                       // stage s + exchange visible

        const float* bp = dsm + stage * SSTAGE;
        float4 hp4 = sp[s & 1][t], hq4 = sq[s & 1][t];
        if (t == 0 && s == 0) hq4.w = -TINF;   // seed: virtual ca[-1][-1]

        float P[8] = {hp4.x, hp4.y, hp4.z, hp4.w, p[0], p[1], p[2], p[3]};
        float Q[8] = {hq4.x, hq4.y, hq4.z, hq4.w, q[0], q[1], q[2], q[3]};
        float CC[4][8];
        #pragma unroll
        for (int k = 0; k < 4; ++k) {
            float4 h = *(const float4*)(bp + k * SROW + j0);       // cols j0-4..j0-1
            float4 o = *(const float4*)(bp + k * SROW + 4 + j0);   // cols j0..j0+3
            CC[k][0] = h.x; CC[k][1] = h.y; CC[k][2] = h.z; CC[k][3] = h.w;
            CC[k][4] = o.x; CC[k][5] = o.y; CC[k][6] = o.z; CC[k][7] = o.w;
        }

        float A[8], B[8], C[8], D[8];
        #pragma unroll
        for (int i = 1; i < 8; ++i)
            A[i] = fmaxf(CC[0][i], fminf(fminf(P[i], P[i-1]), Q[i-1]));
        #pragma unroll
        for (int i = 2; i < 8; ++i)
            B[i] = fmaxf(CC[1][i], fminf(fminf(A[i], A[i-1]), P[i-1]));
        #pragma unroll
        for (int i = 3; i < 8; ++i)
            C[i] = fmaxf(CC[2][i], fminf(fminf(B[i], B[i-1]), A[i-1]));
        #pragma unroll
        for (int i = 4; i < 8; ++i)
            D[i] = fmaxf(CC[3][i], fminf(fminf(C[i], C[i-1]), B[i-1]));

        sp[(s + 1) & 1][t + 1] = make_float4(D[4], D[5], D[6], D[7]);
        sq[(s + 1) & 1][t + 1] = make_float4(C[4], C[5], C[6], C[7]);
        if (s == 511) res = C[7];              // diag 2046, col 1023 @ t=255

        p[0] = D[4]; p[1] = D[5]; p[2] = D[6]; p[3] = D[7];
        q[0] = C[4]; q[1] = C[5]; q[2] = C[6]; q[3] = C[7];

        // Issue stage s+9 into the buffer consumed at body s-1 (race-free).
        {
            int st2 = stage + (RING - 1); if (st2 >= RING) st2 -= RING;
            const float* src = SCo + (size_t)(4 * (s + RING - 1)) * RS;
            unsigned d = smu + st2 * (SSTAGE * 4);
            #pragma unroll
            for (int k = 0; k < 4; ++k)
                cpa16(d + k * (SROW * 4), src + (size_t)k * RS);
            asm volatile("cp.async.commit_group;");
        }
        if (++stage == RING) stage = 0;
    }

    if (t == 255) g_bdist[b] = res;
}

// ---------------------------------------------------------------------------
// Kernel 4: mean over batches.
// ---------------------------------------------------------------------------
__global__ void reduce_kernel(float* out) {
    float v = g_bdist[threadIdx.x];
    #pragma unroll
    for (int o = 16; o > 0; o >>= 1) v += __shfl_down_sync(0xffffffffu, v, o);
    if (threadIdx.x == 0) out[0] = v * (1.0f / BB);
}

// ---------------------------------------------------------------------------
extern "C" void kernel_launch(void* const* d_in, const int* in_sizes, int n_in,
                              void* d_out, int out_size) {
    const float* pred = (const float*)d_in[0];
    const float* targ = (const float*)d_in[1];
    (void)in_sizes; (void)n_in; (void)out_size;

    cudaFuncSetAttribute(dp_kernel,
                         cudaFuncAttributeMaxDynamicSharedMemorySize, DPDYN);

    dim3 ig(2047, BB);
    init_kernel<<<ig, 256>>>();
    norms_kernel<<<8192, 256>>>(pred, targ);
    dim3 cg(8, 8, 32);
    cost_kernel<<<cg, 256>>>(pred, targ);
    dp_kernel<<<32, 256, DPDYN>>>();
    reduce_kernel<<<1, 32>>>((float*)d_out);
}

// round 11
// speedup vs baseline: 1.1772x; 1.1772x over previous
#include <cuda_runtime.h>
#include <math.h>

#define TINF 3.0e38f
#define TT   1024
#define BB   32
#define DDIM 64
#define RS   1024        // floats per diag row (128B-aligned rows)
#define DROWS 2048       // rows 0..2046 used; predicate caps loads at 2047

// Diag-major cost [b][d][j]. Valid cells written by cost_kernel; the ~2
// boundary cells per row (j=d+1, j=d-1024) pre-set TINF by binit_kernel.
// Deep-invalid cells stay uninitialized: provably never reach a valid cell
// (valid cells' sources are valid-or-boundary only; fmin/fmax NaN-safe).
__device__ float g_cost[(size_t)BB * DROWS * RS];
__device__ float g_n2[2 * BB * TT];
__device__ float g_bdist[BB];

// ---------------------------------------------------------------------------
// Kernel 0: boundary-only init. Cell (d, d+1) = virtual row i=-1;
// cell (d, d-1024) = virtual row i=1024. 65K scalar writes total.
// ---------------------------------------------------------------------------
__global__ void binit_kernel() {
    int i = blockIdx.x * blockDim.x + threadIdx.x;
    int b = i >> 11, d = i & 2047;
    if (b >= BB) return;
    float* row = g_cost + ((size_t)b * DROWS + d) * RS;
    if (d <= 1022)                  row[d + 1]    = TINF;
    else if (d >= 1024 && d <= 2046) row[d - 1024] = TINF;
}

// ---------------------------------------------------------------------------
// Kernel 1: squared row norms. One warp per 64-dim row.
// ---------------------------------------------------------------------------
__global__ void norms_kernel(const float* __restrict__ pred,
                             const float* __restrict__ targ) {
    int gw   = (blockIdx.x * blockDim.x + threadIdx.x) >> 5;
    int lane = threadIdx.x & 31;
    if (gw >= 2 * BB * TT) return;
    const float* src = (gw < BB * TT) ? (pred + (size_t)gw * DDIM)
                                      : (targ + (size_t)(gw - BB * TT) * DDIM);
    float x0 = src[lane], x1 = src[lane + 32];
    float s = x0 * x0 + x1 * x1;
    #pragma unroll
    for (int o = 16; o > 0; o >>= 1) s += __shfl_down_sync(0xffffffffu, s, o);
    if (lane == 0) g_n2[gw] = s;
}

// ---------------------------------------------------------------------------
// Kernel 2: TF32 tensor-core cost tiles (unchanged from R7).
// ---------------------------------------------------------------------------
__device__ __forceinline__ unsigned f2tf(float x) {
    unsigned u;
    asm("cvt.rna.tf32.f32 %0, %1;" : "=r"(u) : "f"(x));
    return u;
}
__device__ __forceinline__ void mma_tf32(float c[4], const unsigned a[4],
                                         const unsigned b[2]) {
    asm volatile(
        "mma.sync.aligned.m16n8k8.row.col.f32.tf32.tf32.f32 "
        "{%0,%1,%2,%3}, {%4,%5,%6,%7}, {%8,%9}, {%0,%1,%2,%3};"
        : "+f"(c[0]), "+f"(c[1]), "+f"(c[2]), "+f"(c[3])
        : "r"(a[0]), "r"(a[1]), "r"(a[2]), "r"(a[3]), "r"(b[0]), "r"(b[1]));
}

#define SKP 36   // smem k-stride (32 + 4 pad)

__global__ void __launch_bounds__(256, 2) cost_kernel(const float* __restrict__ pred,
                                                      const float* __restrict__ targ) {
    int b  = blockIdx.z;
    int i0 = blockIdx.y * 128, j0 = blockIdx.x * 128;
    const float* A  = pred + (size_t)b * TT * DDIM;
    const float* Bm = targ + (size_t)b * TT * DDIM;

    __shared__ __align__(16) float smbuf[2 * 128 * SKP];   // 36864 B
    float* sA = smbuf;
    float* sB = smbuf + 128 * SKP;
    float* Cs = smbuf;                                     // reused in epilogue

    int tid  = threadIdx.x;
    int lane = tid & 31, w = tid >> 5;
    int g    = lane >> 2, tig = lane & 3;
    int wm   = (w & 3) * 32, wn = (w >> 2) * 64;

    float c[2][8][4];
    #pragma unroll
    for (int mt = 0; mt < 2; ++mt)
        #pragma unroll
        for (int nt = 0; nt < 8; ++nt)
            #pragma unroll
            for (int e = 0; e < 4; ++e) c[mt][nt][e] = 0.f;

    int lr = tid >> 1;
    int lk = (tid & 1) * 16;
    const float* ga = A  + (size_t)(i0 + lr) * DDIM + lk;
    const float* gb = Bm + (size_t)(j0 + lr) * DDIM + lk;

    #pragma unroll 1
    for (int kc = 0; kc < 64; kc += 32) {
        #pragma unroll
        for (int c4 = 0; c4 < 4; ++c4) {
            float4 va = *(const float4*)(ga + kc + c4 * 4);
            float4 vb = *(const float4*)(gb + kc + c4 * 4);
            int o = lr * SKP + lk + c4 * 4;
            sA[o + 0] = __uint_as_float(f2tf(va.x));
            sA[o + 1] = __uint_as_float(f2tf(va.y));
            sA[o + 2] = __uint_as_float(f2tf(va.z));
            sA[o + 3] = __uint_as_float(f2tf(va.w));
            sB[o + 0] = __uint_as_float(f2tf(vb.x));
            sB[o + 1] = __uint_as_float(f2tf(vb.y));
            sB[o + 2] = __uint_as_float(f2tf(vb.z));
            sB[o + 3] = __uint_as_float(f2tf(vb.w));
        }
        __syncthreads();

        #pragma unroll
        for (int ks = 0; ks < 32; ks += 8) {
            unsigned af[2][4], bf[8][2];
            #pragma unroll
            for (int mt = 0; mt < 2; ++mt) {
                int mr = wm + mt * 16;
                af[mt][0] = __float_as_uint(sA[(mr + g)     * SKP + ks + tig]);
                af[mt][1] = __float_as_uint(sA[(mr + g + 8) * SKP + ks + tig]);
                af[mt][2] = __float_as_uint(sA[(mr + g)     * SKP + ks + tig + 4]);
                af[mt][3] = __float_as_uint(sA[(mr + g + 8) * SKP + ks + tig + 4]);
            }
            #pragma unroll
            for (int nt = 0; nt < 8; ++nt) {
                int nr = wn + nt * 8 + g;
                bf[nt][0] = __float_as_uint(sB[nr * SKP + ks + tig]);
                bf[nt][1] = __float_as_uint(sB[nr * SKP + ks + tig + 4]);
            }
            #pragma unroll
            for (int mt = 0; mt < 2; ++mt)
                #pragma unroll
                for (int nt = 0; nt < 8; ++nt)
                    mma_tf32(c[mt][nt], af[mt], bf[nt]);
        }
        __syncthreads();
    }

    float a2v[2][2], b2v[8][2];
    #pragma unroll
    for (int mt = 0; mt < 2; ++mt) {
        a2v[mt][0] = g_n2[b * TT + i0 + wm + mt * 16 + g];
        a2v[mt][1] = g_n2[b * TT + i0 + wm + mt * 16 + g + 8];
    }
    #pragma unroll
    for (int nt = 0; nt < 8; ++nt) {
        b2v[nt][0] = g_n2[BB * TT + b * TT + j0 + wn + nt * 8 + 2 * tig];
        b2v[nt][1] = g_n2[BB * TT + b * TT + j0 + wn + nt * 8 + 2 * tig + 1];
    }

    float* out = g_cost + (size_t)b * DROWS * RS;

    #pragma unroll 1
    for (int qq = 0; qq < 4; ++qq) {
        int qi = qq >> 1, qj = qq & 1;
        __syncthreads();
        if ((w >> 2) == qj && ((w & 3) >> 1) == qi) {
            int mloc0 = ((w & 3) & 1) * 32;
            #pragma unroll
            for (int mt = 0; mt < 2; ++mt) {
                int ml = mloc0 + mt * 16 + g;
                #pragma unroll
                for (int nt = 0; nt < 8; ++nt) {
                    int nl = nt * 8 + 2 * tig;
                    float s0 = a2v[mt][0] + b2v[nt][0] - 2.0f * c[mt][nt][0];
                    float s1 = a2v[mt][0] + b2v[nt][1] - 2.0f * c[mt][nt][1];
                    float s2 = a2v[mt][1] + b2v[nt][0] - 2.0f * c[mt][nt][2];
                    float s3 = a2v[mt][1] + b2v[nt][1] - 2.0f * c[mt][nt][3];
                    Cs[ml * 66 + nl]           = sqrtf(fmaxf(s0, 1e-12f));
                    Cs[ml * 66 + nl + 1]       = sqrtf(fmaxf(s1, 1e-12f));
                    Cs[(ml + 8) * 66 + nl]     = sqrtf(fmaxf(s2, 1e-12f));
                    Cs[(ml + 8) * 66 + nl + 1] = sqrtf(fmaxf(s3, 1e-12f));
                }
            }
        }
        __syncthreads();

        int i0q = i0 + qi * 64, j0q = j0 + qj * 64;
        int D0 = i0q + j0q;
        for (int dd = w; dd < 127; dd += 8) {
            int jl = max(0, dd - 63);
            int jh = min(dd, 63);
            int L = jh - jl + 1;
            size_t gbase = (size_t)(D0 + dd) * RS + (size_t)(j0q + jl);
            for (int l = lane; l < L; l += 32) {
                int j = jl + l;
                out[gbase + l] = Cs[(dd - j) * 66 + j];
            }
        }
    }
}

// ---------------------------------------------------------------------------
// Kernel 3: wavefront DP, 10-stage cp.async pipeline, LOADS PREDICATED to
// the useful band d in [j0-1, j0+1027]: rows outside contain only
// deep-invalid cells whose values provably never reach a valid cell
// (boundary cells carry TINF from binit; fmin/fmax are NaN-discarding).
// Halves DRAM read traffic and smem fill traffic. Superstep math unchanged.
// ---------------------------------------------------------------------------
#define RING    10
#define SROW    1028                 // floats per staged row (4 guard + 1024)
#define SSTAGE  (4 * SROW)           // floats per stage
#define DPDYN   (RING * SSTAGE * 4)  // dynamic smem bytes (164,480)

__device__ __forceinline__ void cpa16(unsigned dst, const float* src) {
    asm volatile("cp.async.cg.shared.global [%0], [%1], 16;"
                 :: "r"(dst), "l"(src));
}

__global__ void __launch_bounds__(256, 1) dp_kernel() {
    extern __shared__ float dsm[];
    int b  = blockIdx.x;
    int t  = threadIdx.x;
    int j0 = t << 2;
    const float* SCo = g_cost + (size_t)b * DROWS * RS + j0;

    __shared__ float4 sp[2][257], sq[2][257];
    for (int i = t; i < 2 * 257; i += 256) {
        (&sp[0][0])[i] = make_float4(TINF, TINF, TINF, TINF);
        (&sq[0][0])[i] = make_float4(TINF, TINF, TINF, TINF);
    }
    for (int i = t; i < RING * 4; i += 256) {     // per-row TINF guards
        float* gr = dsm + i * SROW;
        gr[0] = TINF; gr[1] = TINF; gr[2] = TINF; gr[3] = TINF;
    }
    __syncthreads();

    unsigned smu = (unsigned)__cvta_generic_to_shared(dsm) + (4 + j0) * 4;

    // Band predicate: row d useful for this thread's staged quad iff
    // d in [j0-1, j0+1027]  <=>  (unsigned)(d - j0 + 1) <= 1028.
    #define DP_ON(d) ((unsigned)((d) - j0 + 1) <= 1028u)

    // Prologue: issue stages 0..8 (one commit group per stage).
    for (int s = 0; s < RING - 1; ++s) {
        const float* src = SCo + (size_t)(4 * s) * RS;
        unsigned d = smu + s * (SSTAGE * 4);
        #pragma unroll
        for (int k = 0; k < 4; ++k)
            if (DP_ON(4 * s + k)) cpa16(d + k * (SROW * 4), src + (size_t)k * RS);
        asm volatile("cp.async.commit_group;");
    }

    float p[4] = {TINF, TINF, TINF, TINF};
    float q[4] = {TINF, TINF, TINF, TINF};
    float res  = 0.f;
    int stage  = 0;

    // 520 supersteps x 4 diagonals = 2080 >= 2047.
    #pragma unroll 1
    for (int s = 0; s < 520; ++s) {
        asm volatile("cp.async.wait_group 8;");
        __syncthreads();                       // stage s + exchange visible

        const float* bp = dsm + stage * SSTAGE;
        float4 hp4 = sp[s & 1][t], hq4 = sq[s & 1][t];
        if (t == 0 && s == 0) hq4.w = -TINF;   // seed: virtual ca[-1][-1]

        float P[8] = {hp4.x, hp4.y, hp4.z, hp4.w, p[0], p[1], p[2], p[3]};
        float Q[8] = {hq4.x, hq4.y, hq4.z, hq4.w, q[0], q[1], q[2], q[3]};
        float CC[4][8];
        #pragma unroll
        for (int k = 0; k < 4; ++k) {
            float4 h = *(const float4*)(bp + k * SROW + j0);       // cols j0-4..j0-1
            float4 o = *(const float4*)(bp + k * SROW + 4 + j0);   // cols j0..j0+3
            CC[k][0] = h.x; CC[k][1] = h.y; CC[k][2] = h.z; CC[k][3] = h.w;
            CC[k][4] = o.x; CC[k][5] = o.y; CC[k][6] = o.z; CC[k][7] = o.w;
        }

        float A[8], B[8], C[8], D[8];
        #pragma unroll
        for (int i = 1; i < 8; ++i)
            A[i] = fmaxf(CC[0][i], fminf(fminf(P[i], P[i-1]), Q[i-1]));
        #pragma unroll
        for (int i = 2; i < 8; ++i)
            B[i] = fmaxf(CC[1][i], fminf(fminf(A[i], A[i-1]), P[i-1]));
        #pragma unroll
        for (int i = 3; i < 8; ++i)
            C[i] = fmaxf(CC[2][i], fminf(fminf(B[i], B[i-1]), A[i-1]));
        #pragma unroll
        for (int i = 4; i < 8; ++i)
            D[i] = fmaxf(CC[3][i], fminf(fminf(C[i], C[i-1]), B[i-1]));

        sp[(s + 1) & 1][t + 1] = make_float4(D[4], D[5], D[6], D[7]);
        sq[(s + 1) & 1][t + 1] = make_float4(C[4], C[5], C[6], C[7]);
        if (s == 511) res = C[7];              // diag 2046, col 1023 @ t=255

        p[0] = D[4]; p[1] = D[5]; p[2] = D[6]; p[3] = D[7];
        q[0] = C[4]; q[1] = C[5]; q[2] = C[6]; q[3] = C[7];

        // Issue stage s+9 into the buffer consumed at body s-1 (race-free).
        {
            int st2 = stage + (RING - 1); if (st2 >= RING) st2 -= RING;
            int dbase = 4 * (s + RING - 1);
            const float* src = SCo + (size_t)dbase * RS;
            unsigned d = smu + st2 * (SSTAGE * 4);
            #pragma unroll
            for (int k = 0; k < 4; ++k)
                if (DP_ON(dbase + k)) cpa16(d + k * (SROW * 4), src + (size_t)k * RS);
            asm volatile("cp.async.commit_group;");
        }
        if (++stage == RING) stage = 0;
    }

    if (t == 255) g_bdist[b] = res;
    #undef DP_ON
}

// ---------------------------------------------------------------------------
// Kernel 4: mean over batches.
// ---------------------------------------------------------------------------
__global__ void reduce_kernel(float* out) {
    float v = g_bdist[threadIdx.x];
    #pragma unroll
    for (int o = 16; o > 0; o >>= 1) v += __shfl_down_sync(0xffffffffu, v, o);
    if (threadIdx.x == 0) out[0] = v * (1.0f / BB);
}

// ---------------------------------------------------------------------------
extern "C" void kernel_launch(void* const* d_in, const int* in_sizes, int n_in,
                              void* d_out, int out_size) {
    const float* pred = (const float*)d_in[0];
    const float* targ = (const float*)d_in[1];
    (void)in_sizes; (void)n_in; (void)out_size;

    cudaFuncSetAttribute(dp_kernel,
                         cudaFuncAttributeMaxDynamicSharedMemorySize, DPDYN);

    binit_kernel<<<256, 256>>>();
    norms_kernel<<<8192, 256>>>(pred, targ);
    dim3 cg(8, 8, 32);
    cost_kernel<<<cg, 256>>>(pred, targ);
    dp_kernel<<<32, 256, DPDYN>>>();
    reduce_kernel<<<1, 32>>>((float*)d_out);
}